// round 3
// baseline (speedup 1.0000x reference)
#include <cuda_runtime.h>
#include <cuda_bf16.h>

#define N_NODES   1000000
#define NUM_GRAPHS 1024

// Scratch (device globals: no allocations allowed)
__device__ float d_agg[N_NODES];      // per-node aggregated sum
__device__ float d_gsum[NUM_GRAPHS];  // per-graph sum of relu(agg)
__device__ float d_gcnt[NUM_GRAPHS];  // per-graph node count
__device__ int   d_is64;              // 1 if indices are int64, 0 if int32

// ---------------------------------------------------------------------------
// Detect index dtype. JAX with x64 disabled silently downcasts int64->int32.
// If data is int32, an int64-reinterpreted word is (lo, hi) with hi ~ U[0,1e6)
// -> value >= 2^32 with overwhelming probability. True int64 indices < 1e6.
// ---------------------------------------------------------------------------
__global__ void detect_kernel(const void* __restrict__ edges) {
    const unsigned long long* p = (const unsigned long long*)edges;
    int is64 = 1;
    #pragma unroll
    for (int i = 0; i < 8; i++)
        if (p[i] >= (1ull << 32)) is64 = 0;
    d_is64 = is64;
}

// ---------------------------------------------------------------------------
// Zero scratch
// ---------------------------------------------------------------------------
__global__ void zero_kernel() {
    int i = blockIdx.x * blockDim.x + threadIdx.x;
    if (i < N_NODES) d_agg[i] = 0.0f;
    if (i < NUM_GRAPHS) { d_gsum[i] = 0.0f; d_gcnt[i] = 0.0f; }
}

// ---------------------------------------------------------------------------
// Edge scatter: agg[dst[e]] += x[src[e]].  4 edges / thread, vectorized loads.
// edge_index layout: [2, E] row-major -> src = [0,E), dst = [E, 2E).
// ---------------------------------------------------------------------------
__global__ void edge_kernel(const void* __restrict__ edge_ptr,
                            const float* __restrict__ x,
                            long long n_edges) {
    long long t    = (long long)blockIdx.x * blockDim.x + threadIdx.x;
    long long base = t * 4;
    if (base >= n_edges) return;

    int s[4], d[4];
    if (d_is64) {
        const longlong2* src2 = (const longlong2*)edge_ptr;             // 2 idx / 16B
        const longlong2* dst2 = src2 + (n_edges >> 1);
        longlong2 a = __ldg(&src2[base >> 1]);
        longlong2 b = __ldg(&src2[(base >> 1) + 1]);
        longlong2 c = __ldg(&dst2[base >> 1]);
        longlong2 e = __ldg(&dst2[(base >> 1) + 1]);
        s[0] = (int)a.x; s[1] = (int)a.y; s[2] = (int)b.x; s[3] = (int)b.y;
        d[0] = (int)c.x; d[1] = (int)c.y; d[2] = (int)e.x; d[3] = (int)e.y;
    } else {
        const int4* src4 = (const int4*)edge_ptr;                        // 4 idx / 16B
        const int4* dst4 = (const int4*)((const int*)edge_ptr + n_edges);
        int4 a = __ldg(&src4[base >> 2]);
        int4 c = __ldg(&dst4[base >> 2]);
        s[0] = a.x; s[1] = a.y; s[2] = a.z; s[3] = a.w;
        d[0] = c.x; d[1] = c.y; d[2] = c.z; d[3] = c.w;
    }

    #pragma unroll
    for (int k = 0; k < 4; k++) {
        if (base + k < n_edges) {
            float xv = __ldg(&x[s[k]]);
            atomicAdd(&d_agg[d[k]], xv);   // result unused -> RED.E.ADD.F32
        }
    }
}

// ---------------------------------------------------------------------------
// ReLU + segmented pool. batch is SORTED, so each thread takes a contiguous
// run of 16 nodes, accumulates locally, and flushes to per-graph atomics only
// on graph-id change (~2 flushes/thread vs 16 raw atomics -> avoids
// single-address L2 atomic serialization).
// ---------------------------------------------------------------------------
#define NODES_PER_THREAD 16
__global__ void pool_kernel(const void* __restrict__ batch_ptr) {
    long long t    = (long long)blockIdx.x * blockDim.x + threadIdx.x;
    long long base = t * NODES_PER_THREAD;
    if (base >= N_NODES) return;
    const int is64 = d_is64;

    int cur = -1;
    float s = 0.0f, c = 0.0f;
    #pragma unroll
    for (int k = 0; k < NODES_PER_THREAD; k++) {
        long long i = base + k;
        if (i >= N_NODES) break;
        int g = is64 ? (int)((const long long*)batch_ptr)[i]
                     : ((const int*)batch_ptr)[i];
        float h = d_agg[i];
        h = h > 0.0f ? h : 0.0f;
        if (g != cur) {
            if (cur >= 0) {
                atomicAdd(&d_gsum[cur], s);
                atomicAdd(&d_gcnt[cur], c);
            }
            cur = g; s = 0.0f; c = 0.0f;
        }
        s += h; c += 1.0f;
    }
    if (cur >= 0) {
        atomicAdd(&d_gsum[cur], s);
        atomicAdd(&d_gcnt[cur], c);
    }
}

// ---------------------------------------------------------------------------
// out[g] = (gsum[g] / max(gcnt[g], 1)) * W[0,0] + b[0]
// ---------------------------------------------------------------------------
__global__ void out_kernel(const float* __restrict__ W,
                           const float* __restrict__ b,
                           float* __restrict__ out) {
    int g = blockIdx.x * blockDim.x + threadIdx.x;
    if (g < NUM_GRAPHS) {
        float cnt = fmaxf(d_gcnt[g], 1.0f);
        out[g] = (d_gsum[g] / cnt) * W[0] + b[0];
    }
}

extern "C" void kernel_launch(void* const* d_in, const int* in_sizes, int n_in,
                              void* d_out, int out_size) {
    const float* x     = (const float*)d_in[0];
    const float* W     = (const float*)d_in[1];
    const float* b     = (const float*)d_in[2];
    const void*  edges = d_in[3];
    const void*  batch = d_in[4];
    long long n_edges  = (long long)in_sizes[3] / 2;   // [2, E] -> E

    detect_kernel<<<1, 1>>>(edges);
    zero_kernel<<<(N_NODES + 255) / 256, 256>>>();

    long long edge_threads = (n_edges + 3) / 4;
    edge_kernel<<<(int)((edge_threads + 255) / 256), 256>>>(edges, x, n_edges);

    long long pool_threads = (N_NODES + NODES_PER_THREAD - 1) / NODES_PER_THREAD;
    pool_kernel<<<(int)((pool_threads + 255) / 256), 256>>>(batch);

    out_kernel<<<(NUM_GRAPHS + 255) / 256, 256>>>(W, b, (float*)d_out);
}